// round 13
// baseline (speedup 1.0000x reference)
#include <cuda_runtime.h>
#include <cuda_bf16.h>
#include <math.h>
#include <stdint.h>

#define BATCH 4
#define CH    384
#define IMG   128
#define HWN   (IMG*IMG)      // 16384
#define NH    8
#define HD    48
#define NBH   (BATCH*NH)     // 32
#define GRAM_CHUNKS 32
#define NCHUNK (HWN/GRAM_CHUNKS)
#define KTOT  384

// ---------------- scratch (device globals; no allocation) ----------------
__device__ __align__(16) float g_pre  [3ull*BATCH*CH*HWN];
__device__ __align__(16) float g_post [3ull*BATCH*CH*HWN];
__device__ __align__(16) float g_snp  [2*BATCH*CH*16];
__device__ __align__(16) float g_sqn  [2*BATCH*CH];
__device__ __align__(16) float g_gpart[(size_t)GRAM_CHUNKS*NBH*HD*HD];
__device__ __align__(16) float g_gram [NBH*HD*HD];
// bf16 split operands
__device__ __align__(16) unsigned short g_wh  [(size_t)1536*KTOT];
__device__ __align__(16) unsigned short g_wl  [(size_t)1536*KTOT];
__device__ __align__(16) unsigned short g_inth[(size_t)2*BATCH*HWN*CH];  // [inp][b][p][c]
__device__ __align__(16) unsigned short g_intl[(size_t)2*BATCH*HWN*CH];
__device__ __align__(16) unsigned short g_avh [(size_t)BATCH*HWN*CH];    // [b][p][c]
__device__ __align__(16) unsigned short g_avl [(size_t)BATCH*HWN*CH];

// ---------------- PTX helpers (sm_80-level only) ----------------
__device__ __forceinline__ uint32_t smem_u32(const void* p) {
    uint32_t a;
    asm("{ .reg .u64 t; cvta.to.shared.u64 t, %1; cvt.u32.u64 %0, t; }" : "=r"(a) : "l"(p));
    return a;
}
__device__ __forceinline__ void cpa16(uint32_t saddr, const void* gptr) {
    asm volatile("cp.async.cg.shared.global [%0], [%1], 16;" :: "r"(saddr), "l"(gptr));
}
__device__ __forceinline__ void ldm_x4(uint32_t* r, uint32_t addr) {
    asm volatile("ldmatrix.sync.aligned.m8n8.x4.shared.b16 {%0,%1,%2,%3}, [%4];"
        : "=r"(r[0]), "=r"(r[1]), "=r"(r[2]), "=r"(r[3]) : "r"(addr));
}
__device__ __forceinline__ void mma_bf16(float* c, const uint32_t* a, const uint32_t* b) {
    asm volatile("mma.sync.aligned.m16n8k16.row.col.f32.bf16.bf16.f32 "
        "{%0,%1,%2,%3}, {%4,%5,%6,%7}, {%8,%9}, {%0,%1,%2,%3};"
        : "+f"(c[0]), "+f"(c[1]), "+f"(c[2]), "+f"(c[3])
        : "r"(a[0]), "r"(a[1]), "r"(a[2]), "r"(a[3]), "r"(b[0]), "r"(b[1]));
}

// ---------------- mma.sync bf16x3 GEMM: C[128x128] tile, 512 thr, 32x32/warp ----------------
#define BM 128
#define BN 128
#define BK 32
#define KITERS (KTOT/BK)       // 12
#define REGB   10240
#define STAGEB 40960
#define GEMM_SMEM (2*STAGEB)   // 81920

__device__ __forceinline__ void gemm_bf16x3(
    const unsigned short* __restrict__ Ah, const unsigned short* __restrict__ Al,
    const unsigned short* __restrict__ Bh, const unsigned short* __restrict__ Bl,
    float* __restrict__ Y)
{
    extern __shared__ char gsm[];
    const uint32_t smem_base = smem_u32(gsm);
    const int tid = threadIdx.x, wid = tid >> 5, lane = tid & 31;
    const int mBase = (wid >> 2) * 32;       // 4 warp-rows of 32
    const int nBase = (wid & 3) * 32;        // 4 warp-cols of 32

    const int aRow = lane & 15, aCol = lane >> 4;
    // B ldmatrix.x4 lane mapping: 16 rows x two 16B k-halves
    const int bRow16 = (lane & 7) + ((lane >> 3) & 1) * 8;
    const int bK16   = (lane >> 4) * 16;

    float acc[2][4][4];
#pragma unroll
    for (int mt = 0; mt < 2; mt++)
#pragma unroll
        for (int nt = 0; nt < 4; nt++)
#pragma unroll
            for (int q = 0; q < 4; q++) acc[mt][nt][q] = 0.f;

    auto load_stage = [&](int st, int k0) {
        const uint32_t sb = smem_base + (st & 1) * STAGEB;
#pragma unroll
        for (int j = 0; j < 4; j++) {
            const int idx = tid + 512 * j;
            const int region = idx >> 9;
            const int rem = idx & 511;
            const int r = rem >> 2, c = rem & 3;
            const uint32_t saddr = sb + region * REGB + r * 80 + c * 16;
            const unsigned short* gsrc;
            if      (region == 0) gsrc = Ah + (size_t)r * KTOT + k0 + c * 8;
            else if (region == 1) gsrc = Al + (size_t)r * KTOT + k0 + c * 8;
            else if (region == 2) gsrc = Bh + (size_t)r * KTOT + k0 + c * 8;
            else                  gsrc = Bl + (size_t)r * KTOT + k0 + c * 8;
            cpa16(saddr, gsrc);
        }
        asm volatile("cp.async.commit_group;" ::: "memory");
    };

    load_stage(0, 0);

    for (int it = 0; it < KITERS; it++) {
        if (it + 1 < KITERS) {
            load_stage(it + 1, (it + 1) * BK);
            asm volatile("cp.async.wait_group 1;" ::: "memory");
        } else {
            asm volatile("cp.async.wait_group 0;" ::: "memory");
        }
        __syncthreads();

        const uint32_t sb  = smem_base + (it & 1) * STAGEB;
        const uint32_t sAh = sb, sAl = sb + REGB, sBh = sb + 2*REGB, sBl = sb + 3*REGB;

#pragma unroll
        for (int ks = 0; ks < 2; ks++) {
            const uint32_t akb = ks * 32 + aCol * 16;
            const uint32_t bkb = ks * 32 + bK16;
            // B fragments: 2 x ldmatrix.x4 per split (16 rows x both k-halves)
            uint32_t fBh[4][2], fBl[4][2];
#pragma unroll
            for (int nt2 = 0; nt2 < 2; nt2++) {
                uint32_t q[4];
                ldm_x4(q, sBh + (uint32_t)(nBase + nt2*16 + bRow16) * 80 + bkb);
                fBh[2*nt2+0][0] = q[0]; fBh[2*nt2+1][0] = q[1];
                fBh[2*nt2+0][1] = q[2]; fBh[2*nt2+1][1] = q[3];
            }
#pragma unroll
            for (int nt2 = 0; nt2 < 2; nt2++) {
                uint32_t q[4];
                ldm_x4(q, sBl + (uint32_t)(nBase + nt2*16 + bRow16) * 80 + bkb);
                fBl[2*nt2+0][0] = q[0]; fBl[2*nt2+1][0] = q[1];
                fBl[2*nt2+0][1] = q[2]; fBl[2*nt2+1][1] = q[3];
            }
#pragma unroll
            for (int mt = 0; mt < 2; mt++) {
                uint32_t aH[4], aL[4];
                ldm_x4(aH, sAh + (uint32_t)(mBase + mt*16 + aRow) * 80 + akb);
#pragma unroll
                for (int nt = 0; nt < 4; nt++) mma_bf16(acc[mt][nt], aH, fBh[nt]);
#pragma unroll
                for (int nt = 0; nt < 4; nt++) mma_bf16(acc[mt][nt], aH, fBl[nt]);
                ldm_x4(aL, sAl + (uint32_t)(mBase + mt*16 + aRow) * 80 + akb);
#pragma unroll
                for (int nt = 0; nt < 4; nt++) mma_bf16(acc[mt][nt], aL, fBh[nt]);
            }
        }
        __syncthreads();
    }

    const int gr = lane >> 2, gc = (lane & 3) * 2;
#pragma unroll
    for (int mt = 0; mt < 2; mt++) {
#pragma unroll
        for (int nt = 0; nt < 4; nt++) {
            float* d0 = Y + (size_t)(mBase + mt*16 + gr) * HWN + nBase + nt*8 + gc;
            d0[0] = acc[mt][nt][0]; d0[1] = acc[mt][nt][1];
            float* d1 = d0 + 8 * HWN;
            d1[0] = acc[mt][nt][2]; d1[1] = acc[mt][nt][3];
        }
    }
}

__global__ __launch_bounds__(512, 2)
void qkv_gemm_tc()
{
    const int z = blockIdx.z, s = z >> 2, b = z & 3;
    const int row0 = blockIdx.y * BM, n0 = blockIdx.x * BN;
    const size_t aoff = (size_t)(s * CH + row0) * KTOT;
    const int inp = (s == 0) ? 1 : 0;   // q comes from message
    const size_t boff = ((size_t)(inp * BATCH + b) * HWN + n0) * KTOT;
    float* Y = g_pre + ((size_t)z * CH + row0) * HWN + n0;
    gemm_bf16x3(g_wh + aoff, g_wl + aoff, g_inth + boff, g_intl + boff, Y);
}

__global__ __launch_bounds__(512, 2)
void proj_gemm_tc(float* __restrict__ out)
{
    const int b = blockIdx.z;
    const int row0 = blockIdx.y * BM, n0 = blockIdx.x * BN;
    const size_t aoff = (size_t)(1152 + row0) * KTOT;
    const size_t boff = ((size_t)b * HWN + n0) * KTOT;
    float* Y = out + ((size_t)b * CH + row0) * HWN + n0;
    gemm_bf16x3(g_wh + aoff, g_wl + aoff, g_avh + boff, g_avl + boff, Y);
}

// ---------------- convert weights to bf16 hi/lo ----------------
__global__ __launch_bounds__(256) void wconv_kernel(const float* __restrict__ wqkv,
                                                    const float* __restrict__ wproj)
{
    const size_t i = (size_t)blockIdx.x * 256 + threadIdx.x;
    const float f = (i < (size_t)1152 * KTOT) ? wqkv[i] : wproj[i - (size_t)1152 * KTOT];
    const uint32_t bits = __float_as_uint(f);
    const float hi = __uint_as_float(bits & 0xFFFF0000u);
    const __nv_bfloat16 lo = __float2bfloat16(f - hi);
    g_wh[i] = (unsigned short)(bits >> 16);
    g_wl[i] = *(const unsigned short*)&lo;
}

// ---------------- transpose + convert one input ----------------
__global__ __launch_bounds__(256) void trx_kernel(const float* __restrict__ src0, int inp)
{
    __shared__ float t[32][33];
    const int b = blockIdx.z;
    const int p0 = blockIdx.x * 32, c0 = blockIdx.y * 32;
    const int tx = threadIdx.x, ty = threadIdx.y;
    const float* src = src0 + ((size_t)b * CH + c0) * HWN + p0;
    for (int yy = ty; yy < 32; yy += 8) t[yy][tx] = src[(size_t)yy * HWN + tx];
    __syncthreads();
    const int z = inp * BATCH + b;
    unsigned short* dh = g_inth + ((size_t)z * HWN + p0) * CH + c0;
    unsigned short* dl = g_intl + ((size_t)z * HWN + p0) * CH + c0;
    for (int yy = ty; yy < 32; yy += 8) {
        const float f = t[tx][yy];
        const uint32_t bits = __float_as_uint(f);
        const float hi = __uint_as_float(bits & 0xFFFF0000u);
        const __nv_bfloat16 lo = __float2bfloat16(f - hi);
        dh[(size_t)yy * CH + tx] = (unsigned short)(bits >> 16);
        dl[(size_t)yy * CH + tx] = *(const unsigned short*)&lo;
    }
}

// ---------------- depthwise 3x3: warp-per-row, shfl horizontal neighbors ----------------
__global__ __launch_bounds__(256)
void dwconv_kernel(const float* __restrict__ wdw)
{
    __shared__ float red[8];

    const int zc = blockIdx.z;
    const int z  = zc / CH;
    const int c  = zc % CH;
    const int s  = z / BATCH;
    const float* wk = wdw + (size_t)(s*CH + c) * 9;
    const float* in   = g_pre  + (size_t)zc * HWN;
    float*       outp = g_post + (size_t)zc * HWN;

    float w[9];
#pragma unroll
    for (int i = 0; i < 9; i++) w[i] = __ldg(&wk[i]);

    const int lane = threadIdx.x;
    const int wy   = threadIdx.y;
    const int px0 = lane * 4;
    const int py  = blockIdx.y * 8 + wy;

    float r[3][6];
#pragma unroll
    for (int ky = 0; ky < 3; ky++) {
        const int iy = py + ky - 1;
        if (iy < 0 || iy >= IMG) {
#pragma unroll
            for (int e = 0; e < 6; e++) r[ky][e] = 0.f;
        } else {
            const float4 v = *(const float4*)(in + (size_t)iy * IMG + px0);
            float left  = __shfl_up_sync(0xffffffffu, v.w, 1);
            float right = __shfl_down_sync(0xffffffffu, v.x, 1);
            if (lane == 0)  left  = 0.f;
            if (lane == 31) right = 0.f;
            r[ky][0] = left;  r[ky][1] = v.x; r[ky][2] = v.y;
            r[ky][3] = v.z;   r[ky][4] = v.w; r[ky][5] = right;
        }
    }

    float a0 = 0.f, a1 = 0.f, a2 = 0.f, a3 = 0.f;
#pragma unroll
    for (int ky = 0; ky < 3; ky++) {
#pragma unroll
        for (int kx = 0; kx < 3; kx++) {
            const float wv = w[ky*3 + kx];
            a0 += r[ky][0 + kx] * wv;
            a1 += r[ky][1 + kx] * wv;
            a2 += r[ky][2 + kx] * wv;
            a3 += r[ky][3 + kx] * wv;
        }
    }
    *(float4*)(outp + (size_t)py * IMG + px0) = make_float4(a0, a1, a2, a3);

    float loc = a0*a0 + a1*a1 + a2*a2 + a3*a3;
    const int tid = wy * 32 + lane;
#pragma unroll
    for (int o = 16; o > 0; o >>= 1) loc += __shfl_xor_sync(0xffffffffu, loc, o);
    if ((tid & 31) == 0) red[tid >> 5] = loc;
    __syncthreads();
    if (tid == 0 && s < 2) {
        float t = 0.f;
#pragma unroll
        for (int i = 0; i < 8; i++) t += red[i];
        g_snp[(size_t)zc * 16 + blockIdx.y] = t;
    }
}

// ---------------- reduce sqnorm partials ----------------
__global__ __launch_bounds__(256)
void sqnorm_kernel()
{
    const int r = blockIdx.x * 256 + threadIdx.x;
    if (r >= 2*BATCH*CH) return;
    float s = 0.f;
#pragma unroll
    for (int i = 0; i < 16; i++) s += g_snp[(size_t)r * 16 + i];
    g_sqn[r] = s;
}

// ---------------- Gram partials: 8x8 threads, 6x6 per thread ----------------
__global__ __launch_bounds__(64)
void gram_kernel()
{
    __shared__ __align__(16) float qs[48][65];
    __shared__ __align__(16) float ks[48][65];

    const int bh = blockIdx.y;
    const int b  = bh >> 3;
    const int h  = bh & 7;
    const int n0 = blockIdx.x * NCHUNK;
    const float* qbase = g_post + ((size_t)(0*BATCH + b)*CH + h*HD) * HWN;
    const float* kbase = g_post + ((size_t)(1*BATCH + b)*CH + h*HD) * HWN;
    const int tid = threadIdx.y * 8 + threadIdx.x;
    const int i0 = threadIdx.y * 6;
    const int j0 = threadIdx.x * 6;

    float acc[6][6];
#pragma unroll
    for (int r = 0; r < 6; r++)
#pragma unroll
        for (int c = 0; c < 6; c++) acc[r][c] = 0.f;

    for (int t = 0; t < NCHUNK; t += 64) {
        for (int e = tid; e < 48*16; e += 64) {
            const int i = e >> 4, j4 = (e & 15) * 4;
            const float4 qv = *(const float4*)&qbase[(size_t)i*HWN + n0 + t + j4];
            const float4 kv = *(const float4*)&kbase[(size_t)i*HWN + n0 + t + j4];
            qs[i][j4+0] = qv.x; qs[i][j4+1] = qv.y; qs[i][j4+2] = qv.z; qs[i][j4+3] = qv.w;
            ks[i][j4+0] = kv.x; ks[i][j4+1] = kv.y; ks[i][j4+2] = kv.z; ks[i][j4+3] = kv.w;
        }
        __syncthreads();
#pragma unroll 4
        for (int nn = 0; nn < 64; nn++) {
            float q[6], k[6];
#pragma unroll
            for (int r = 0; r < 6; r++) q[r] = qs[i0+r][nn];
#pragma unroll
            for (int c = 0; c < 6; c++) k[c] = ks[j0+c][nn];
#pragma unroll
            for (int r = 0; r < 6; r++)
#pragma unroll
                for (int c = 0; c < 6; c++) acc[r][c] += q[r] * k[c];
        }
        __syncthreads();
    }

    float* gp = g_gpart + ((size_t)blockIdx.x * NBH + bh) * (HD*HD);
#pragma unroll
    for (int r = 0; r < 6; r++)
#pragma unroll
        for (int c = 0; c < 6; c++)
            gp[(i0+r)*HD + (j0+c)] = acc[r][c];
}

__global__ __launch_bounds__(1024)
void gram_reduce_kernel()
{
    const int idx = blockIdx.x * 1024 + threadIdx.x;
    float s = 0.f;
#pragma unroll
    for (int ch = 0; ch < GRAM_CHUNKS; ch++)
        s += g_gpart[(size_t)ch * NBH * (HD*HD) + idx];
    g_gram[idx] = s;
}

// ---------------- normalize + temperature + softmax ----------------
__global__ __launch_bounds__(64)
void softmax_kernel(const float* __restrict__ temp)
{
    const int bh = blockIdx.x;
    const int b  = bh >> 3;
    const int h  = bh & 7;
    const int i  = threadIdx.x;
    if (i >= HD) return;

    float* gg = g_gram + (size_t)bh * (HD*HD) + i*HD;
    const float invq = rsqrtf(fmaxf(g_sqn[b*CH + h*HD + i], 1e-24f));
    const float T = temp[h];

    float row[HD];
    float m = -3.4e38f;
#pragma unroll
    for (int j = 0; j < HD; j++) {
        const float invk = rsqrtf(fmaxf(g_sqn[(BATCH + b)*CH + h*HD + j], 1e-24f));
        const float v = gg[j] * invq * invk * T;
        row[j] = v;
        m = fmaxf(m, v);
    }
    float sum = 0.f;
#pragma unroll
    for (int j = 0; j < HD; j++) { row[j] = expf(row[j] - m); sum += row[j]; }
    const float inv = 1.f / sum;
#pragma unroll
    for (int j = 0; j < HD; j++) gg[j] = row[j] * inv;
}

// ---------------- A@V with smem-staged coalesced bf16 hi/lo stores ----------------
#define AVPAD 49
#define AV_SMEM ((HD*HD + 256*AVPAD) * 4)   // 59392 B

__global__ __launch_bounds__(256)
void av_kernel()
{
    extern __shared__ float avdyn[];
    float* As   = avdyn;
    float* sacc = avdyn + HD*HD;

    const int bh = blockIdx.y;
    const int b  = bh >> 3;
    const int h  = bh & 7;
    const int tid = threadIdx.x;
    const int n0 = blockIdx.x * 256;
    const int n = n0 + tid;

    for (int e = tid; e < HD*HD; e += 256) As[e] = g_gram[(size_t)bh * (HD*HD) + e];
    __syncthreads();

    const float* vbase = g_post + ((size_t)(2*BATCH + b)*CH + h*HD) * HWN + n;
    float acc[HD];
#pragma unroll
    for (int i = 0; i < HD; i++) acc[i] = 0.f;

#pragma unroll 4
    for (int j = 0; j < HD; j++) {
        const float vj = __ldg(&vbase[(size_t)j * HWN]);
#pragma unroll
        for (int i = 0; i < HD; i++) acc[i] += As[i*HD + j] * vj;
    }

#pragma unroll
    for (int i = 0; i < HD; i++) sacc[tid * AVPAD + i] = acc[i];
    __syncthreads();

    unsigned short* dhb = g_avh + ((size_t)b * HWN + n0) * CH + h*HD;
    unsigned short* dlb = g_avl + ((size_t)b * HWN + n0) * CH + h*HD;
#pragma unroll
    for (int k = 0; k < 24; k++) {
        const int wv = tid + k * 256;
        const int p  = wv / 24;
        const int cw = wv % 24;
        const float f0 = sacc[p * AVPAD + 2*cw];
        const float f1 = sacc[p * AVPAD + 2*cw + 1];
        const uint32_t b0 = __float_as_uint(f0);
        const uint32_t b1 = __float_as_uint(f1);
        const uint32_t hiw = (b0 >> 16) | (b1 & 0xFFFF0000u);
        *(uint32_t*)(dhb + (size_t)p * CH + 2*cw) = hiw;
        const float h0 = __uint_as_float(b0 & 0xFFFF0000u);
        const float h1 = __uint_as_float(b1 & 0xFFFF0000u);
        const __nv_bfloat16 l0 = __float2bfloat16(f0 - h0);
        const __nv_bfloat16 l1 = __float2bfloat16(f1 - h1);
        const uint32_t low = (uint32_t)(*(const unsigned short*)&l0)
                           | ((uint32_t)(*(const unsigned short*)&l1) << 16);
        *(uint32_t*)(dlb + (size_t)p * CH + 2*cw) = low;
    }
}

// ---------------- launch ----------------
extern "C" void kernel_launch(void* const* d_in, const int* in_sizes, int n_in,
                              void* d_out, int out_size)
{
    const float* x      = (const float*)d_in[0];
    const float* msg    = (const float*)d_in[1];
    const float* w_qkv  = (const float*)d_in[2];
    const float* w_dw   = (const float*)d_in[3];
    const float* w_proj = (const float*)d_in[4];
    const float* temp   = (const float*)d_in[5];
    float* out = (float*)d_out;

    cudaFuncSetAttribute(qkv_gemm_tc, cudaFuncAttributeMaxDynamicSharedMemorySize, GEMM_SMEM);
    cudaFuncSetAttribute(proj_gemm_tc, cudaFuncAttributeMaxDynamicSharedMemorySize, GEMM_SMEM);
    cudaFuncSetAttribute(av_kernel,   cudaFuncAttributeMaxDynamicSharedMemorySize, AV_SMEM);

    // 0. bf16 hi/lo conversions (trx split so qkv_gemm is launch #4 for ncu)
    wconv_kernel<<<(1536*KTOT)/256, 256>>>(w_qkv, w_proj);
    trx_kernel<<<dim3(HWN/32, CH/32, BATCH), dim3(32,8)>>>(x, 0);
    trx_kernel<<<dim3(HWN/32, CH/32, BATCH), dim3(32,8)>>>(msg, 1);
    // 1. qkv GEMMs on tensor cores (512 thr, 32x32/warp, 2 CTA/SM)
    qkv_gemm_tc<<<dim3(HWN/BN, CH/BM, 3*BATCH), 512, GEMM_SMEM>>>();
    // 2. depthwise 3x3 (warp-per-row + shfl, fused sqnorm partials)
    dwconv_kernel<<<dim3(1, IMG/8, 3*BATCH*CH), dim3(32,8)>>>(w_dw);
    // 3. reduce sqnorm partials
    sqnorm_kernel<<<(2*BATCH*CH + 255)/256, 256>>>();
    // 4-5. Gram (two-phase deterministic, 6x6 register tiles)
    gram_kernel<<<dim3(GRAM_CHUNKS, NBH), dim3(8,8)>>>();
    gram_reduce_kernel<<<(NBH*HD*HD)/1024, 1024>>>();
    // 6. softmax
    softmax_kernel<<<NBH, 64>>>(temp);
    // 7. A@V (smem-staged coalesced bf16 hi/lo stores)
    av_kernel<<<dim3(HWN/256, NBH), 256, AV_SMEM>>>();
    // 8. output projection on tensor cores
    proj_gemm_tc<<<dim3(HWN/BN, CH/BM, BATCH), 512, GEMM_SMEM>>>(out);
}

// round 14
// speedup vs baseline: 1.0155x; 1.0155x over previous
#include <cuda_runtime.h>
#include <cuda_bf16.h>
#include <math.h>
#include <stdint.h>

#define BATCH 4
#define CH    384
#define IMG   128
#define HWN   (IMG*IMG)      // 16384
#define NH    8
#define HD    48
#define NBH   (BATCH*NH)     // 32
#define GRAM_CHUNKS 32
#define NCHUNK (HWN/GRAM_CHUNKS)
#define KTOT  384

// ---------------- scratch (device globals; no allocation) ----------------
__device__ __align__(16) float g_pre  [3ull*BATCH*CH*HWN];
__device__ __align__(16) float g_post [3ull*BATCH*CH*HWN];
__device__ __align__(16) float g_snp  [2*BATCH*CH*16];
__device__ __align__(16) float g_sqn  [2*BATCH*CH];
__device__ __align__(16) float g_gpart[(size_t)GRAM_CHUNKS*NBH*HD*HD];
__device__ __align__(16) float g_gram [NBH*HD*HD];
// bf16 split operands
__device__ __align__(16) unsigned short g_wh  [(size_t)1536*KTOT];
__device__ __align__(16) unsigned short g_wl  [(size_t)1536*KTOT];
__device__ __align__(16) unsigned short g_inth[(size_t)2*BATCH*HWN*CH];  // [inp][b][p][c]
__device__ __align__(16) unsigned short g_intl[(size_t)2*BATCH*HWN*CH];
__device__ __align__(16) unsigned short g_avh [(size_t)BATCH*HWN*CH];    // [b][p][c]
__device__ __align__(16) unsigned short g_avl [(size_t)BATCH*HWN*CH];

// ---------------- PTX helpers (sm_80-level only) ----------------
__device__ __forceinline__ uint32_t smem_u32(const void* p) {
    uint32_t a;
    asm("{ .reg .u64 t; cvta.to.shared.u64 t, %1; cvt.u32.u64 %0, t; }" : "=r"(a) : "l"(p));
    return a;
}
__device__ __forceinline__ void cpa16(uint32_t saddr, const void* gptr) {
    asm volatile("cp.async.cg.shared.global [%0], [%1], 16;" :: "r"(saddr), "l"(gptr));
}
__device__ __forceinline__ void ldm_x4(uint32_t* r, uint32_t addr) {
    asm volatile("ldmatrix.sync.aligned.m8n8.x4.shared.b16 {%0,%1,%2,%3}, [%4];"
        : "=r"(r[0]), "=r"(r[1]), "=r"(r[2]), "=r"(r[3]) : "r"(addr));
}
__device__ __forceinline__ void mma_bf16(float* c, const uint32_t* a, const uint32_t* b) {
    asm volatile("mma.sync.aligned.m16n8k16.row.col.f32.bf16.bf16.f32 "
        "{%0,%1,%2,%3}, {%4,%5,%6,%7}, {%8,%9}, {%0,%1,%2,%3};"
        : "+f"(c[0]), "+f"(c[1]), "+f"(c[2]), "+f"(c[3])
        : "r"(a[0]), "r"(a[1]), "r"(a[2]), "r"(a[3]), "r"(b[0]), "r"(b[1]));
}

// ---------------- mma.sync bf16x3 GEMM: C[128x128], 256 thr, 64x32 warp tiles ----------------
#define BM 128
#define BN 128
#define BK 32
#define KITERS (KTOT/BK)       // 12
#define REGB   10240
#define STAGEB 40960
#define GEMM_SMEM (2*STAGEB)   // 81920

__device__ __forceinline__ void gemm_bf16x3(
    const unsigned short* __restrict__ Ah, const unsigned short* __restrict__ Al,
    const unsigned short* __restrict__ Bh, const unsigned short* __restrict__ Bl,
    float* __restrict__ Y)
{
    extern __shared__ char gsm[];
    const uint32_t smem_base = smem_u32(gsm);
    const int tid = threadIdx.x, wid = tid >> 5, lane = tid & 31;
    const int mBase = (wid >> 2) * 64;       // 2 warp-rows of 64
    const int nBase = (wid & 3) * 32;        // 4 warp-cols of 32

    const int aRow = lane & 15, aCol = lane >> 4;
    // B ldmatrix.x4 lane mapping: 16 rows x two 16B k-halves (validated in R13)
    const int bRow16 = (lane & 7) + ((lane >> 3) & 1) * 8;
    const int bK16   = (lane >> 4) * 16;

    float acc[4][4][4];
#pragma unroll
    for (int mt = 0; mt < 4; mt++)
#pragma unroll
        for (int nt = 0; nt < 4; nt++)
#pragma unroll
            for (int q = 0; q < 4; q++) acc[mt][nt][q] = 0.f;

    auto load_stage = [&](int st, int k0) {
        const uint32_t sb = smem_base + (st & 1) * STAGEB;
#pragma unroll
        for (int j = 0; j < 8; j++) {
            const int idx = tid + 256 * j;
            const int region = idx >> 9;
            const int rem = idx & 511;
            const int r = rem >> 2, c = rem & 3;
            const uint32_t saddr = sb + region * REGB + r * 80 + c * 16;
            const unsigned short* gsrc;
            if      (region == 0) gsrc = Ah + (size_t)r * KTOT + k0 + c * 8;
            else if (region == 1) gsrc = Al + (size_t)r * KTOT + k0 + c * 8;
            else if (region == 2) gsrc = Bh + (size_t)r * KTOT + k0 + c * 8;
            else                  gsrc = Bl + (size_t)r * KTOT + k0 + c * 8;
            cpa16(saddr, gsrc);
        }
        asm volatile("cp.async.commit_group;" ::: "memory");
    };

    load_stage(0, 0);

    for (int it = 0; it < KITERS; it++) {
        if (it + 1 < KITERS) {
            load_stage(it + 1, (it + 1) * BK);
            asm volatile("cp.async.wait_group 1;" ::: "memory");
        } else {
            asm volatile("cp.async.wait_group 0;" ::: "memory");
        }
        __syncthreads();

        const uint32_t sb  = smem_base + (it & 1) * STAGEB;
        const uint32_t sAh = sb, sAl = sb + REGB, sBh = sb + 2*REGB, sBl = sb + 3*REGB;

#pragma unroll
        for (int ks = 0; ks < 2; ks++) {
            const uint32_t akb = ks * 32 + aCol * 16;
            const uint32_t bkb = ks * 32 + bK16;
            // B fragments via ldmatrix.x4 (2 per split instead of 4 x2)
            uint32_t fBh[4][2], fBl[4][2];
#pragma unroll
            for (int nt2 = 0; nt2 < 2; nt2++) {
                uint32_t q[4];
                ldm_x4(q, sBh + (uint32_t)(nBase + nt2*16 + bRow16) * 80 + bkb);
                fBh[2*nt2+0][0] = q[0]; fBh[2*nt2+1][0] = q[1];
                fBh[2*nt2+0][1] = q[2]; fBh[2*nt2+1][1] = q[3];
            }
#pragma unroll
            for (int nt2 = 0; nt2 < 2; nt2++) {
                uint32_t q[4];
                ldm_x4(q, sBl + (uint32_t)(nBase + nt2*16 + bRow16) * 80 + bkb);
                fBl[2*nt2+0][0] = q[0]; fBl[2*nt2+1][0] = q[1];
                fBl[2*nt2+0][1] = q[2]; fBl[2*nt2+1][1] = q[3];
            }
            // A streamed per warp-row tile (R11 order, bitwise-identical)
#pragma unroll
            for (int mt = 0; mt < 4; mt++) {
                uint32_t aH[4], aL[4];
                ldm_x4(aH, sAh + (uint32_t)(mBase + mt*16 + aRow) * 80 + akb);
#pragma unroll
                for (int nt = 0; nt < 4; nt++) mma_bf16(acc[mt][nt], aH, fBh[nt]);
#pragma unroll
                for (int nt = 0; nt < 4; nt++) mma_bf16(acc[mt][nt], aH, fBl[nt]);
                ldm_x4(aL, sAl + (uint32_t)(mBase + mt*16 + aRow) * 80 + akb);
#pragma unroll
                for (int nt = 0; nt < 4; nt++) mma_bf16(acc[mt][nt], aL, fBh[nt]);
            }
        }
        __syncthreads();
    }

    const int gr = lane >> 2, gc = (lane & 3) * 2;
#pragma unroll
    for (int mt = 0; mt < 4; mt++) {
#pragma unroll
        for (int nt = 0; nt < 4; nt++) {
            float* d0 = Y + (size_t)(mBase + mt*16 + gr) * HWN + nBase + nt*8 + gc;
            d0[0] = acc[mt][nt][0]; d0[1] = acc[mt][nt][1];
            float* d1 = d0 + 8 * HWN;
            d1[0] = acc[mt][nt][2]; d1[1] = acc[mt][nt][3];
        }
    }
}

__global__ __launch_bounds__(256, 2)
void qkv_gemm_tc()
{
    const int z = blockIdx.z, s = z >> 2, b = z & 3;
    const int row0 = blockIdx.y * BM, n0 = blockIdx.x * BN;
    const size_t aoff = (size_t)(s * CH + row0) * KTOT;
    const int inp = (s == 0) ? 1 : 0;   // q comes from message
    const size_t boff = ((size_t)(inp * BATCH + b) * HWN + n0) * KTOT;
    float* Y = g_pre + ((size_t)z * CH + row0) * HWN + n0;
    gemm_bf16x3(g_wh + aoff, g_wl + aoff, g_inth + boff, g_intl + boff, Y);
}

__global__ __launch_bounds__(256, 2)
void proj_gemm_tc(float* __restrict__ out)
{
    const int b = blockIdx.z;
    const int row0 = blockIdx.y * BM, n0 = blockIdx.x * BN;
    const size_t aoff = (size_t)(1152 + row0) * KTOT;
    const size_t boff = ((size_t)b * HWN + n0) * KTOT;
    float* Y = out + ((size_t)b * CH + row0) * HWN + n0;
    gemm_bf16x3(g_wh + aoff, g_wl + aoff, g_avh + boff, g_avl + boff, Y);
}

// ---------------- convert weights to bf16 hi/lo ----------------
__global__ __launch_bounds__(256) void wconv_kernel(const float* __restrict__ wqkv,
                                                    const float* __restrict__ wproj)
{
    const size_t i = (size_t)blockIdx.x * 256 + threadIdx.x;
    const float f = (i < (size_t)1152 * KTOT) ? wqkv[i] : wproj[i - (size_t)1152 * KTOT];
    const uint32_t bits = __float_as_uint(f);
    const float hi = __uint_as_float(bits & 0xFFFF0000u);
    const __nv_bfloat16 lo = __float2bfloat16(f - hi);
    g_wh[i] = (unsigned short)(bits >> 16);
    g_wl[i] = *(const unsigned short*)&lo;
}

// ---------------- transpose + convert one input ----------------
__global__ __launch_bounds__(256) void trx_kernel(const float* __restrict__ src0, int inp)
{
    __shared__ float t[32][33];
    const int b = blockIdx.z;
    const int p0 = blockIdx.x * 32, c0 = blockIdx.y * 32;
    const int tx = threadIdx.x, ty = threadIdx.y;
    const float* src = src0 + ((size_t)b * CH + c0) * HWN + p0;
    for (int yy = ty; yy < 32; yy += 8) t[yy][tx] = src[(size_t)yy * HWN + tx];
    __syncthreads();
    const int z = inp * BATCH + b;
    unsigned short* dh = g_inth + ((size_t)z * HWN + p0) * CH + c0;
    unsigned short* dl = g_intl + ((size_t)z * HWN + p0) * CH + c0;
    for (int yy = ty; yy < 32; yy += 8) {
        const float f = t[tx][yy];
        const uint32_t bits = __float_as_uint(f);
        const float hi = __uint_as_float(bits & 0xFFFF0000u);
        const __nv_bfloat16 lo = __float2bfloat16(f - hi);
        dh[(size_t)yy * CH + tx] = (unsigned short)(bits >> 16);
        dl[(size_t)yy * CH + tx] = *(const unsigned short*)&lo;
    }
}

// ---------------- depthwise 3x3: warp-per-row, shfl horizontal neighbors ----------------
__global__ __launch_bounds__(256)
void dwconv_kernel(const float* __restrict__ wdw)
{
    __shared__ float red[8];

    const int zc = blockIdx.z;
    const int z  = zc / CH;
    const int c  = zc % CH;
    const int s  = z / BATCH;
    const float* wk = wdw + (size_t)(s*CH + c) * 9;
    const float* in   = g_pre  + (size_t)zc * HWN;
    float*       outp = g_post + (size_t)zc * HWN;

    float w[9];
#pragma unroll
    for (int i = 0; i < 9; i++) w[i] = __ldg(&wk[i]);

    const int lane = threadIdx.x;
    const int wy   = threadIdx.y;
    const int px0 = lane * 4;
    const int py  = blockIdx.y * 8 + wy;

    float r[3][6];
#pragma unroll
    for (int ky = 0; ky < 3; ky++) {
        const int iy = py + ky - 1;
        if (iy < 0 || iy >= IMG) {
#pragma unroll
            for (int e = 0; e < 6; e++) r[ky][e] = 0.f;
        } else {
            const float4 v = *(const float4*)(in + (size_t)iy * IMG + px0);
            float left  = __shfl_up_sync(0xffffffffu, v.w, 1);
            float right = __shfl_down_sync(0xffffffffu, v.x, 1);
            if (lane == 0)  left  = 0.f;
            if (lane == 31) right = 0.f;
            r[ky][0] = left;  r[ky][1] = v.x; r[ky][2] = v.y;
            r[ky][3] = v.z;   r[ky][4] = v.w; r[ky][5] = right;
        }
    }

    float a0 = 0.f, a1 = 0.f, a2 = 0.f, a3 = 0.f;
#pragma unroll
    for (int ky = 0; ky < 3; ky++) {
#pragma unroll
        for (int kx = 0; kx < 3; kx++) {
            const float wv = w[ky*3 + kx];
            a0 += r[ky][0 + kx] * wv;
            a1 += r[ky][1 + kx] * wv;
            a2 += r[ky][2 + kx] * wv;
            a3 += r[ky][3 + kx] * wv;
        }
    }
    *(float4*)(outp + (size_t)py * IMG + px0) = make_float4(a0, a1, a2, a3);

    float loc = a0*a0 + a1*a1 + a2*a2 + a3*a3;
    const int tid = wy * 32 + lane;
#pragma unroll
    for (int o = 16; o > 0; o >>= 1) loc += __shfl_xor_sync(0xffffffffu, loc, o);
    if ((tid & 31) == 0) red[tid >> 5] = loc;
    __syncthreads();
    if (tid == 0 && s < 2) {
        float t = 0.f;
#pragma unroll
        for (int i = 0; i < 8; i++) t += red[i];
        g_snp[(size_t)zc * 16 + blockIdx.y] = t;
    }
}

// ---------------- reduce sqnorm partials ----------------
__global__ __launch_bounds__(256)
void sqnorm_kernel()
{
    const int r = blockIdx.x * 256 + threadIdx.x;
    if (r >= 2*BATCH*CH) return;
    float s = 0.f;
#pragma unroll
    for (int i = 0; i < 16; i++) s += g_snp[(size_t)r * 16 + i];
    g_sqn[r] = s;
}

// ---------------- Gram partials: 8x8 threads, 6x6 per thread ----------------
__global__ __launch_bounds__(64)
void gram_kernel()
{
    __shared__ __align__(16) float qs[48][65];
    __shared__ __align__(16) float ks[48][65];

    const int bh = blockIdx.y;
    const int b  = bh >> 3;
    const int h  = bh & 7;
    const int n0 = blockIdx.x * NCHUNK;
    const float* qbase = g_post + ((size_t)(0*BATCH + b)*CH + h*HD) * HWN;
    const float* kbase = g_post + ((size_t)(1*BATCH + b)*CH + h*HD) * HWN;
    const int tid = threadIdx.y * 8 + threadIdx.x;
    const int i0 = threadIdx.y * 6;
    const int j0 = threadIdx.x * 6;

    float acc[6][6];
#pragma unroll
    for (int r = 0; r < 6; r++)
#pragma unroll
        for (int c = 0; c < 6; c++) acc[r][c] = 0.f;

    for (int t = 0; t < NCHUNK; t += 64) {
        for (int e = tid; e < 48*16; e += 64) {
            const int i = e >> 4, j4 = (e & 15) * 4;
            const float4 qv = *(const float4*)&qbase[(size_t)i*HWN + n0 + t + j4];
            const float4 kv = *(const float4*)&kbase[(size_t)i*HWN + n0 + t + j4];
            qs[i][j4+0] = qv.x; qs[i][j4+1] = qv.y; qs[i][j4+2] = qv.z; qs[i][j4+3] = qv.w;
            ks[i][j4+0] = kv.x; ks[i][j4+1] = kv.y; ks[i][j4+2] = kv.z; ks[i][j4+3] = kv.w;
        }
        __syncthreads();
#pragma unroll 4
        for (int nn = 0; nn < 64; nn++) {
            float q[6], k[6];
#pragma unroll
            for (int r = 0; r < 6; r++) q[r] = qs[i0+r][nn];
#pragma unroll
            for (int c = 0; c < 6; c++) k[c] = ks[j0+c][nn];
#pragma unroll
            for (int r = 0; r < 6; r++)
#pragma unroll
                for (int c = 0; c < 6; c++) acc[r][c] += q[r] * k[c];
        }
        __syncthreads();
    }

    float* gp = g_gpart + ((size_t)blockIdx.x * NBH + bh) * (HD*HD);
#pragma unroll
    for (int r = 0; r < 6; r++)
#pragma unroll
        for (int c = 0; c < 6; c++)
            gp[(i0+r)*HD + (j0+c)] = acc[r][c];
}

__global__ __launch_bounds__(1024)
void gram_reduce_kernel()
{
    const int idx = blockIdx.x * 1024 + threadIdx.x;
    float s = 0.f;
#pragma unroll
    for (int ch = 0; ch < GRAM_CHUNKS; ch++)
        s += g_gpart[(size_t)ch * NBH * (HD*HD) + idx];
    g_gram[idx] = s;
}

// ---------------- normalize + temperature + softmax ----------------
__global__ __launch_bounds__(64)
void softmax_kernel(const float* __restrict__ temp)
{
    const int bh = blockIdx.x;
    const int b  = bh >> 3;
    const int h  = bh & 7;
    const int i  = threadIdx.x;
    if (i >= HD) return;

    float* gg = g_gram + (size_t)bh * (HD*HD) + i*HD;
    const float invq = rsqrtf(fmaxf(g_sqn[b*CH + h*HD + i], 1e-24f));
    const float T = temp[h];

    float row[HD];
    float m = -3.4e38f;
#pragma unroll
    for (int j = 0; j < HD; j++) {
        const float invk = rsqrtf(fmaxf(g_sqn[(BATCH + b)*CH + h*HD + j], 1e-24f));
        const float v = gg[j] * invq * invk * T;
        row[j] = v;
        m = fmaxf(m, v);
    }
    float sum = 0.f;
#pragma unroll
    for (int j = 0; j < HD; j++) { row[j] = expf(row[j] - m); sum += row[j]; }
    const float inv = 1.f / sum;
#pragma unroll
    for (int j = 0; j < HD; j++) gg[j] = row[j] * inv;
}

// ---------------- A@V with smem-staged coalesced bf16 hi/lo stores ----------------
#define AVPAD 49
#define AV_SMEM ((HD*HD + 256*AVPAD) * 4)   // 59392 B

__global__ __launch_bounds__(256)
void av_kernel()
{
    extern __shared__ float avdyn[];
    float* As   = avdyn;
    float* sacc = avdyn + HD*HD;

    const int bh = blockIdx.y;
    const int b  = bh >> 3;
    const int h  = bh & 7;
    const int tid = threadIdx.x;
    const int n0 = blockIdx.x * 256;
    const int n = n0 + tid;

    for (int e = tid; e < HD*HD; e += 256) As[e] = g_gram[(size_t)bh * (HD*HD) + e];
    __syncthreads();

    const float* vbase = g_post + ((size_t)(2*BATCH + b)*CH + h*HD) * HWN + n;
    float acc[HD];
#pragma unroll
    for (int i = 0; i < HD; i++) acc[i] = 0.f;

#pragma unroll 4
    for (int j = 0; j < HD; j++) {
        const float vj = __ldg(&vbase[(size_t)j * HWN]);
#pragma unroll
        for (int i = 0; i < HD; i++) acc[i] += As[i*HD + j] * vj;
    }

#pragma unroll
    for (int i = 0; i < HD; i++) sacc[tid * AVPAD + i] = acc[i];
    __syncthreads();

    unsigned short* dhb = g_avh + ((size_t)b * HWN + n0) * CH + h*HD;
    unsigned short* dlb = g_avl + ((size_t)b * HWN + n0) * CH + h*HD;
#pragma unroll
    for (int k = 0; k < 24; k++) {
        const int wv = tid + k * 256;
        const int p  = wv / 24;
        const int cw = wv % 24;
        const float f0 = sacc[p * AVPAD + 2*cw];
        const float f1 = sacc[p * AVPAD + 2*cw + 1];
        const uint32_t b0 = __float_as_uint(f0);
        const uint32_t b1 = __float_as_uint(f1);
        const uint32_t hiw = (b0 >> 16) | (b1 & 0xFFFF0000u);
        *(uint32_t*)(dhb + (size_t)p * CH + 2*cw) = hiw;
        const float h0 = __uint_as_float(b0 & 0xFFFF0000u);
        const float h1 = __uint_as_float(b1 & 0xFFFF0000u);
        const __nv_bfloat16 l0 = __float2bfloat16(f0 - h0);
        const __nv_bfloat16 l1 = __float2bfloat16(f1 - h1);
        const uint32_t low = (uint32_t)(*(const unsigned short*)&l0)
                           | ((uint32_t)(*(const unsigned short*)&l1) << 16);
        *(uint32_t*)(dlb + (size_t)p * CH + 2*cw) = low;
    }
}

// ---------------- launch ----------------
extern "C" void kernel_launch(void* const* d_in, const int* in_sizes, int n_in,
                              void* d_out, int out_size)
{
    const float* x      = (const float*)d_in[0];
    const float* msg    = (const float*)d_in[1];
    const float* w_qkv  = (const float*)d_in[2];
    const float* w_dw   = (const float*)d_in[3];
    const float* w_proj = (const float*)d_in[4];
    const float* temp   = (const float*)d_in[5];
    float* out = (float*)d_out;

    cudaFuncSetAttribute(qkv_gemm_tc, cudaFuncAttributeMaxDynamicSharedMemorySize, GEMM_SMEM);
    cudaFuncSetAttribute(proj_gemm_tc, cudaFuncAttributeMaxDynamicSharedMemorySize, GEMM_SMEM);
    cudaFuncSetAttribute(av_kernel,   cudaFuncAttributeMaxDynamicSharedMemorySize, AV_SMEM);

    // 0. bf16 hi/lo conversions (trx split so qkv_gemm is launch #4 for ncu)
    wconv_kernel<<<(1536*KTOT)/256, 256>>>(w_qkv, w_proj);
    trx_kernel<<<dim3(HWN/32, CH/32, BATCH), dim3(32,8)>>>(x, 0);
    trx_kernel<<<dim3(HWN/32, CH/32, BATCH), dim3(32,8)>>>(msg, 1);
    // 1. qkv GEMMs on tensor cores (R11 config + ldm.x4 B loads)
    qkv_gemm_tc<<<dim3(HWN/BN, CH/BM, 3*BATCH), 256, GEMM_SMEM>>>();
    // 2. depthwise 3x3 (warp-per-row + shfl, fused sqnorm partials)
    dwconv_kernel<<<dim3(1, IMG/8, 3*BATCH*CH), dim3(32,8)>>>(w_dw);
    // 3. reduce sqnorm partials
    sqnorm_kernel<<<(2*BATCH*CH + 255)/256, 256>>>();
    // 4-5. Gram (two-phase deterministic, 6x6 register tiles)
    gram_kernel<<<dim3(GRAM_CHUNKS, NBH), dim3(8,8)>>>();
    gram_reduce_kernel<<<(NBH*HD*HD)/1024, 1024>>>();
    // 6. softmax
    softmax_kernel<<<NBH, 64>>>(temp);
    // 7. A@V (smem-staged coalesced bf16 hi/lo stores)
    av_kernel<<<dim3(HWN/256, NBH), 256, AV_SMEM>>>();
    // 8. output projection on tensor cores
    proj_gemm_tc<<<dim3(HWN/BN, CH/BM, BATCH), 256, GEMM_SMEM>>>(out);
}

// round 15
// speedup vs baseline: 1.1210x; 1.1039x over previous
#include <cuda_runtime.h>
#include <cuda_bf16.h>
#include <math.h>
#include <stdint.h>

#define BATCH 4
#define CH    384
#define IMG   128
#define HWN   (IMG*IMG)      // 16384
#define NH    8
#define HD    48
#define NBH   (BATCH*NH)     // 32
#define GRAM_CHUNKS 32
#define NCHUNK (HWN/GRAM_CHUNKS)
#define KTOT  384

// ---------------- scratch (device globals; no allocation) ----------------
__device__ __align__(16) float g_pre  [3ull*BATCH*CH*HWN];
__device__ __align__(16) float g_post [3ull*BATCH*CH*HWN];
__device__ __align__(16) float g_snp  [2*BATCH*CH*16];
__device__ __align__(16) float g_sqn  [2*BATCH*CH];
__device__ __align__(16) float g_gpart[(size_t)GRAM_CHUNKS*NBH*HD*HD];
__device__ __align__(16) float g_gram [NBH*HD*HD];
// bf16 split operands
__device__ __align__(16) unsigned short g_wh  [(size_t)1536*KTOT];
__device__ __align__(16) unsigned short g_wl  [(size_t)1536*KTOT];
__device__ __align__(16) unsigned short g_inth[(size_t)2*BATCH*HWN*CH];  // [inp][b][p][c]
__device__ __align__(16) unsigned short g_intl[(size_t)2*BATCH*HWN*CH];
__device__ __align__(16) unsigned short g_avh [(size_t)BATCH*HWN*CH];    // [b][p][c]
__device__ __align__(16) unsigned short g_avl [(size_t)BATCH*HWN*CH];

// ---------------- PTX helpers (sm_80-level only) ----------------
__device__ __forceinline__ uint32_t smem_u32(const void* p) {
    uint32_t a;
    asm("{ .reg .u64 t; cvta.to.shared.u64 t, %1; cvt.u32.u64 %0, t; }" : "=r"(a) : "l"(p));
    return a;
}
__device__ __forceinline__ void cpa16(uint32_t saddr, const void* gptr) {
    asm volatile("cp.async.cg.shared.global [%0], [%1], 16;" :: "r"(saddr), "l"(gptr));
}
__device__ __forceinline__ void ldm_x4(uint32_t* r, uint32_t addr) {
    asm volatile("ldmatrix.sync.aligned.m8n8.x4.shared.b16 {%0,%1,%2,%3}, [%4];"
        : "=r"(r[0]), "=r"(r[1]), "=r"(r[2]), "=r"(r[3]) : "r"(addr));
}
__device__ __forceinline__ void ldm_x2(uint32_t* r, uint32_t addr) {
    asm volatile("ldmatrix.sync.aligned.m8n8.x2.shared.b16 {%0,%1}, [%2];"
        : "=r"(r[0]), "=r"(r[1]) : "r"(addr));
}
__device__ __forceinline__ void mma_bf16(float* c, const uint32_t* a, const uint32_t* b) {
    asm volatile("mma.sync.aligned.m16n8k16.row.col.f32.bf16.bf16.f32 "
        "{%0,%1,%2,%3}, {%4,%5,%6,%7}, {%8,%9}, {%0,%1,%2,%3};"
        : "+f"(c[0]), "+f"(c[1]), "+f"(c[2]), "+f"(c[3])
        : "r"(a[0]), "r"(a[1]), "r"(a[2]), "r"(a[3]), "r"(b[0]), "r"(b[1]));
}

// ---------------- mma.sync bf16x3 GEMM: C[128 x 128] tile, K=384 (R11 config) ----------------
#define BM 128
#define BN 128
#define BK 32
#define KITERS (KTOT/BK)       // 12
#define REGB   10240
#define STAGEB 40960
#define GEMM_SMEM (2*STAGEB)   // 81920

__device__ __forceinline__ void gemm_bf16x3(
    const unsigned short* __restrict__ Ah, const unsigned short* __restrict__ Al,
    const unsigned short* __restrict__ Bh, const unsigned short* __restrict__ Bl,
    float* __restrict__ Y)
{
    extern __shared__ char gsm[];
    const uint32_t smem_base = smem_u32(gsm);
    const int tid = threadIdx.x, wid = tid >> 5, lane = tid & 31;
    const int mBase = (wid >> 2) * 64;       // 2 warp-rows
    const int nBase = (wid & 3) * 32;        // 4 warp-cols

    const int aRow = lane & 15, aCol = lane >> 4;
    const int i16  = lane & 15;
    const int bRow = i16 & 7,  bCol = i16 >> 3;

    float acc[4][4][4];
#pragma unroll
    for (int mt = 0; mt < 4; mt++)
#pragma unroll
        for (int nt = 0; nt < 4; nt++)
#pragma unroll
            for (int q = 0; q < 4; q++) acc[mt][nt][q] = 0.f;

    auto load_stage = [&](int st, int k0) {
        const uint32_t sb = smem_base + (st & 1) * STAGEB;
#pragma unroll
        for (int j = 0; j < 8; j++) {
            const int idx = tid + 256 * j;
            const int region = idx >> 9;
            const int rem = idx & 511;
            const int r = rem >> 2, c = rem & 3;
            const uint32_t saddr = sb + region * REGB + r * 80 + c * 16;
            const unsigned short* gsrc;
            if      (region == 0) gsrc = Ah + (size_t)r * KTOT + k0 + c * 8;
            else if (region == 1) gsrc = Al + (size_t)r * KTOT + k0 + c * 8;
            else if (region == 2) gsrc = Bh + (size_t)r * KTOT + k0 + c * 8;
            else                  gsrc = Bl + (size_t)r * KTOT + k0 + c * 8;
            cpa16(saddr, gsrc);
        }
        asm volatile("cp.async.commit_group;" ::: "memory");
    };

    load_stage(0, 0);

    for (int it = 0; it < KITERS; it++) {
        if (it + 1 < KITERS) {
            load_stage(it + 1, (it + 1) * BK);
            asm volatile("cp.async.wait_group 1;" ::: "memory");
        } else {
            asm volatile("cp.async.wait_group 0;" ::: "memory");
        }
        __syncthreads();

        const uint32_t sb  = smem_base + (it & 1) * STAGEB;
        const uint32_t sAh = sb, sAl = sb + REGB, sBh = sb + 2*REGB, sBl = sb + 3*REGB;

#pragma unroll
        for (int ks = 0; ks < 2; ks++) {
            const uint32_t akb = ks * 32 + aCol * 16;
            const uint32_t bkb = ks * 32 + bCol * 16;
            // B fragments live across the whole ks-step (16 regs)
            uint32_t fBh[4][2], fBl[4][2];
#pragma unroll
            for (int nt = 0; nt < 4; nt++)
                ldm_x2(fBh[nt], sBh + (uint32_t)(nBase + nt*8 + bRow) * 80 + bkb);
#pragma unroll
            for (int nt = 0; nt < 4; nt++)
                ldm_x2(fBl[nt], sBl + (uint32_t)(nBase + nt*8 + bRow) * 80 + bkb);
            // stream A per warp-row tile: only 8 A-regs live at a time
#pragma unroll
            for (int mt = 0; mt < 4; mt++) {
                uint32_t aH[4], aL[4];
                ldm_x4(aH, sAh + (uint32_t)(mBase + mt*16 + aRow) * 80 + akb);
#pragma unroll
                for (int nt = 0; nt < 4; nt++) mma_bf16(acc[mt][nt], aH, fBh[nt]);
#pragma unroll
                for (int nt = 0; nt < 4; nt++) mma_bf16(acc[mt][nt], aH, fBl[nt]);
                ldm_x4(aL, sAl + (uint32_t)(mBase + mt*16 + aRow) * 80 + akb);
#pragma unroll
                for (int nt = 0; nt < 4; nt++) mma_bf16(acc[mt][nt], aL, fBh[nt]);
            }
        }
        __syncthreads();
    }

    const int gr = lane >> 2, gc = (lane & 3) * 2;
#pragma unroll
    for (int mt = 0; mt < 4; mt++) {
#pragma unroll
        for (int nt = 0; nt < 4; nt++) {
            float* d0 = Y + (size_t)(mBase + mt*16 + gr) * HWN + nBase + nt*8 + gc;
            d0[0] = acc[mt][nt][0]; d0[1] = acc[mt][nt][1];
            float* d1 = d0 + 8 * HWN;
            d1[0] = acc[mt][nt][2]; d1[1] = acc[mt][nt][3];
        }
    }
}

__global__ __launch_bounds__(256, 2)
void qkv_gemm_tc()
{
    const int z = blockIdx.z, s = z >> 2, b = z & 3;
    const int row0 = blockIdx.y * BM, n0 = blockIdx.x * BN;
    const size_t aoff = (size_t)(s * CH + row0) * KTOT;
    const int inp = (s == 0) ? 1 : 0;   // q comes from message
    const size_t boff = ((size_t)(inp * BATCH + b) * HWN + n0) * KTOT;
    float* Y = g_pre + ((size_t)z * CH + row0) * HWN + n0;
    gemm_bf16x3(g_wh + aoff, g_wl + aoff, g_inth + boff, g_intl + boff, Y);
}

__global__ __launch_bounds__(256, 2)
void proj_gemm_tc(float* __restrict__ out)
{
    const int b = blockIdx.z;
    const int row0 = blockIdx.y * BM, n0 = blockIdx.x * BN;
    const size_t aoff = (size_t)(1152 + row0) * KTOT;
    const size_t boff = ((size_t)b * HWN + n0) * KTOT;
    float* Y = out + ((size_t)b * CH + row0) * HWN + n0;
    gemm_bf16x3(g_wh + aoff, g_wl + aoff, g_avh + boff, g_avl + boff, Y);
}

// ---------------- convert weights to bf16 hi/lo ----------------
__global__ __launch_bounds__(256) void wconv_kernel(const float* __restrict__ wqkv,
                                                    const float* __restrict__ wproj)
{
    const size_t i = (size_t)blockIdx.x * 256 + threadIdx.x;
    const float f = (i < (size_t)1152 * KTOT) ? wqkv[i] : wproj[i - (size_t)1152 * KTOT];
    const uint32_t bits = __float_as_uint(f);
    const float hi = __uint_as_float(bits & 0xFFFF0000u);
    const __nv_bfloat16 lo = __float2bfloat16(f - hi);
    g_wh[i] = (unsigned short)(bits >> 16);
    g_wl[i] = *(const unsigned short*)&lo;
}

// ---------------- transpose + convert one input ----------------
__global__ __launch_bounds__(256) void trx_kernel(const float* __restrict__ src0, int inp)
{
    __shared__ float t[32][33];
    const int b = blockIdx.z;
    const int p0 = blockIdx.x * 32, c0 = blockIdx.y * 32;
    const int tx = threadIdx.x, ty = threadIdx.y;
    const float* src = src0 + ((size_t)b * CH + c0) * HWN + p0;
    for (int yy = ty; yy < 32; yy += 8) t[yy][tx] = src[(size_t)yy * HWN + tx];
    __syncthreads();
    const int z = inp * BATCH + b;
    unsigned short* dh = g_inth + ((size_t)z * HWN + p0) * CH + c0;
    unsigned short* dl = g_intl + ((size_t)z * HWN + p0) * CH + c0;
    for (int yy = ty; yy < 32; yy += 8) {
        const float f = t[tx][yy];
        const uint32_t bits = __float_as_uint(f);
        const float hi = __uint_as_float(bits & 0xFFFF0000u);
        const __nv_bfloat16 lo = __float2bfloat16(f - hi);
        dh[(size_t)yy * CH + tx] = (unsigned short)(bits >> 16);
        dl[(size_t)yy * CH + tx] = *(const unsigned short*)&lo;
    }
}

// ---------------- depthwise 3x3: 2 output rows/thread, shfl neighbors ----------------
__global__ __launch_bounds__(256)
void dwconv_kernel(const float* __restrict__ wdw)
{
    __shared__ float red[8];

    const int zc = blockIdx.z;
    const int z  = zc / CH;
    const int c  = zc % CH;
    const int s  = z / BATCH;
    const float* wk = wdw + (size_t)(s*CH + c) * 9;
    const float* in   = g_pre  + (size_t)zc * HWN;
    float*       outp = g_post + (size_t)zc * HWN;

    float w[9];
#pragma unroll
    for (int i = 0; i < 9; i++) w[i] = __ldg(&wk[i]);

    const int lane = threadIdx.x;          // warp = one image row band
    const int wy   = threadIdx.y;          // 0..7 -> 2 rows each
    const int px0 = lane * 4;
    const int py0 = blockIdx.y * 16 + wy * 2;

    // load 4 input rows: py0-1 .. py0+2 (all conditions warp-uniform)
    float r[4][6];
#pragma unroll
    for (int ky = 0; ky < 4; ky++) {
        const int iy = py0 + ky - 1;
        if (iy < 0 || iy >= IMG) {
#pragma unroll
            for (int e = 0; e < 6; e++) r[ky][e] = 0.f;
        } else {
            const float4 v = *(const float4*)(in + (size_t)iy * IMG + px0);
            float left  = __shfl_up_sync(0xffffffffu, v.w, 1);
            float right = __shfl_down_sync(0xffffffffu, v.x, 1);
            if (lane == 0)  left  = 0.f;
            if (lane == 31) right = 0.f;
            r[ky][0] = left;  r[ky][1] = v.x; r[ky][2] = v.y;
            r[ky][3] = v.z;   r[ky][4] = v.w; r[ky][5] = right;
        }
    }

    float loc = 0.f;
#pragma unroll
    for (int row = 0; row < 2; row++) {
        float a0 = 0.f, a1 = 0.f, a2 = 0.f, a3 = 0.f;
#pragma unroll
        for (int ky = 0; ky < 3; ky++) {
#pragma unroll
            for (int kx = 0; kx < 3; kx++) {
                const float wv = w[ky*3 + kx];
                a0 += r[row + ky][0 + kx] * wv;
                a1 += r[row + ky][1 + kx] * wv;
                a2 += r[row + ky][2 + kx] * wv;
                a3 += r[row + ky][3 + kx] * wv;
            }
        }
        *(float4*)(outp + (size_t)(py0 + row) * IMG + px0) = make_float4(a0, a1, a2, a3);
        loc += a0*a0 + a1*a1 + a2*a2 + a3*a3;
    }

    const int tid = wy * 32 + lane;
#pragma unroll
    for (int o = 16; o > 0; o >>= 1) loc += __shfl_xor_sync(0xffffffffu, loc, o);
    if ((tid & 31) == 0) red[tid >> 5] = loc;
    __syncthreads();
    if (tid == 0 && s < 2) {
        float t = 0.f;
#pragma unroll
        for (int i = 0; i < 8; i++) t += red[i];
        g_snp[(size_t)zc * 8 + blockIdx.y] = t;
    }
}

// ---------------- reduce sqnorm partials ----------------
__global__ __launch_bounds__(256)
void sqnorm_kernel()
{
    const int r = blockIdx.x * 256 + threadIdx.x;
    if (r >= 2*BATCH*CH) return;
    float s = 0.f;
#pragma unroll
    for (int i = 0; i < 8; i++) s += g_snp[(size_t)r * 8 + i];
    g_sqn[r] = s;
}

// ---------------- Gram partials: 8x8 threads, 6x6 per thread ----------------
__global__ __launch_bounds__(64)
void gram_kernel()
{
    __shared__ __align__(16) float qs[48][65];
    __shared__ __align__(16) float ks[48][65];

    const int bh = blockIdx.y;
    const int b  = bh >> 3;
    const int h  = bh & 7;
    const int n0 = blockIdx.x * NCHUNK;
    const float* qbase = g_post + ((size_t)(0*BATCH + b)*CH + h*HD) * HWN;
    const float* kbase = g_post + ((size_t)(1*BATCH + b)*CH + h*HD) * HWN;
    const int tid = threadIdx.y * 8 + threadIdx.x;
    const int i0 = threadIdx.y * 6;
    const int j0 = threadIdx.x * 6;

    float acc[6][6];
#pragma unroll
    for (int r = 0; r < 6; r++)
#pragma unroll
        for (int c = 0; c < 6; c++) acc[r][c] = 0.f;

    for (int t = 0; t < NCHUNK; t += 64) {
        for (int e = tid; e < 48*16; e += 64) {
            const int i = e >> 4, j4 = (e & 15) * 4;
            const float4 qv = *(const float4*)&qbase[(size_t)i*HWN + n0 + t + j4];
            const float4 kv = *(const float4*)&kbase[(size_t)i*HWN + n0 + t + j4];
            qs[i][j4+0] = qv.x; qs[i][j4+1] = qv.y; qs[i][j4+2] = qv.z; qs[i][j4+3] = qv.w;
            ks[i][j4+0] = kv.x; ks[i][j4+1] = kv.y; ks[i][j4+2] = kv.z; ks[i][j4+3] = kv.w;
        }
        __syncthreads();
#pragma unroll 4
        for (int nn = 0; nn < 64; nn++) {
            float q[6], k[6];
#pragma unroll
            for (int r = 0; r < 6; r++) q[r] = qs[i0+r][nn];
#pragma unroll
            for (int c = 0; c < 6; c++) k[c] = ks[j0+c][nn];
#pragma unroll
            for (int r = 0; r < 6; r++)
#pragma unroll
                for (int c = 0; c < 6; c++) acc[r][c] += q[r] * k[c];
        }
        __syncthreads();
    }

    float* gp = g_gpart + ((size_t)blockIdx.x * NBH + bh) * (HD*HD);
#pragma unroll
    for (int r = 0; r < 6; r++)
#pragma unroll
        for (int c = 0; c < 6; c++)
            gp[(i0+r)*HD + (j0+c)] = acc[r][c];
}

__global__ __launch_bounds__(1024)
void gram_reduce_kernel()
{
    const int idx = blockIdx.x * 1024 + threadIdx.x;
    float s = 0.f;
#pragma unroll
    for (int ch = 0; ch < GRAM_CHUNKS; ch++)
        s += g_gpart[(size_t)ch * NBH * (HD*HD) + idx];
    g_gram[idx] = s;
}

// ---------------- normalize + temperature + softmax ----------------
__global__ __launch_bounds__(64)
void softmax_kernel(const float* __restrict__ temp)
{
    const int bh = blockIdx.x;
    const int b  = bh >> 3;
    const int h  = bh & 7;
    const int i  = threadIdx.x;
    if (i >= HD) return;

    float* gg = g_gram + (size_t)bh * (HD*HD) + i*HD;
    const float invq = rsqrtf(fmaxf(g_sqn[b*CH + h*HD + i], 1e-24f));
    const float T = temp[h];

    float row[HD];
    float m = -3.4e38f;
#pragma unroll
    for (int j = 0; j < HD; j++) {
        const float invk = rsqrtf(fmaxf(g_sqn[(BATCH + b)*CH + h*HD + j], 1e-24f));
        const float v = gg[j] * invq * invk * T;
        row[j] = v;
        m = fmaxf(m, v);
    }
    float sum = 0.f;
#pragma unroll
    for (int j = 0; j < HD; j++) { row[j] = expf(row[j] - m); sum += row[j]; }
    const float inv = 1.f / sum;
#pragma unroll
    for (int j = 0; j < HD; j++) gg[j] = row[j] * inv;
}

// ---------------- A@V with smem-staged coalesced bf16 hi/lo stores ----------------
#define AVPAD 49
#define AV_SMEM ((HD*HD + 256*AVPAD) * 4)   // 59392 B

__global__ __launch_bounds__(256)
void av_kernel()
{
    extern __shared__ float avdyn[];
    float* As   = avdyn;
    float* sacc = avdyn + HD*HD;

    const int bh = blockIdx.y;
    const int b  = bh >> 3;
    const int h  = bh & 7;
    const int tid = threadIdx.x;
    const int n0 = blockIdx.x * 256;
    const int n = n0 + tid;

    for (int e = tid; e < HD*HD; e += 256) As[e] = g_gram[(size_t)bh * (HD*HD) + e];
    __syncthreads();

    const float* vbase = g_post + ((size_t)(2*BATCH + b)*CH + h*HD) * HWN + n;
    float acc[HD];
#pragma unroll
    for (int i = 0; i < HD; i++) acc[i] = 0.f;

#pragma unroll 4
    for (int j = 0; j < HD; j++) {
        const float vj = __ldg(&vbase[(size_t)j * HWN]);
#pragma unroll
        for (int i = 0; i < HD; i++) acc[i] += As[i*HD + j] * vj;
    }

#pragma unroll
    for (int i = 0; i < HD; i++) sacc[tid * AVPAD + i] = acc[i];
    __syncthreads();

    unsigned short* dhb = g_avh + ((size_t)b * HWN + n0) * CH + h*HD;
    unsigned short* dlb = g_avl + ((size_t)b * HWN + n0) * CH + h*HD;
#pragma unroll
    for (int k = 0; k < 24; k++) {
        const int wv = tid + k * 256;
        const int p  = wv / 24;
        const int cw = wv % 24;
        const float f0 = sacc[p * AVPAD + 2*cw];
        const float f1 = sacc[p * AVPAD + 2*cw + 1];
        const uint32_t b0 = __float_as_uint(f0);
        const uint32_t b1 = __float_as_uint(f1);
        const uint32_t hiw = (b0 >> 16) | (b1 & 0xFFFF0000u);
        *(uint32_t*)(dhb + (size_t)p * CH + 2*cw) = hiw;
        const float h0 = __uint_as_float(b0 & 0xFFFF0000u);
        const float h1 = __uint_as_float(b1 & 0xFFFF0000u);
        const __nv_bfloat16 l0 = __float2bfloat16(f0 - h0);
        const __nv_bfloat16 l1 = __float2bfloat16(f1 - h1);
        const uint32_t low = (uint32_t)(*(const unsigned short*)&l0)
                           | ((uint32_t)(*(const unsigned short*)&l1) << 16);
        *(uint32_t*)(dlb + (size_t)p * CH + 2*cw) = low;
    }
}

// ---------------- launch ----------------
extern "C" void kernel_launch(void* const* d_in, const int* in_sizes, int n_in,
                              void* d_out, int out_size)
{
    const float* x      = (const float*)d_in[0];
    const float* msg    = (const float*)d_in[1];
    const float* w_qkv  = (const float*)d_in[2];
    const float* w_dw   = (const float*)d_in[3];
    const float* w_proj = (const float*)d_in[4];
    const float* temp   = (const float*)d_in[5];
    float* out = (float*)d_out;

    cudaFuncSetAttribute(qkv_gemm_tc, cudaFuncAttributeMaxDynamicSharedMemorySize, GEMM_SMEM);
    cudaFuncSetAttribute(proj_gemm_tc, cudaFuncAttributeMaxDynamicSharedMemorySize, GEMM_SMEM);
    cudaFuncSetAttribute(av_kernel,   cudaFuncAttributeMaxDynamicSharedMemorySize, AV_SMEM);

    // 0. bf16 hi/lo conversions (trx split so qkv_gemm is launch #4 for ncu)
    wconv_kernel<<<(1536*KTOT)/256, 256>>>(w_qkv, w_proj);
    trx_kernel<<<dim3(HWN/32, CH/32, BATCH), dim3(32,8)>>>(x, 0);
    trx_kernel<<<dim3(HWN/32, CH/32, BATCH), dim3(32,8)>>>(msg, 1);
    // 1. qkv GEMMs on tensor cores (R11 config: 256 thr, 64x32 warp tiles, 2 CTA/SM)
    qkv_gemm_tc<<<dim3(HWN/BN, CH/BM, 3*BATCH), 256, GEMM_SMEM>>>();
    // 2. depthwise 3x3 (2 output rows/thread, fused sqnorm partials)
    dwconv_kernel<<<dim3(1, IMG/16, 3*BATCH*CH), dim3(32,8)>>>(w_dw);
    // 3. reduce sqnorm partials
    sqnorm_kernel<<<(2*BATCH*CH + 255)/256, 256>>>();
    // 4-5. Gram (two-phase deterministic, 6x6 register tiles)
    gram_kernel<<<dim3(GRAM_CHUNKS, NBH), dim3(8,8)>>>();
    gram_reduce_kernel<<<(NBH*HD*HD)/1024, 1024>>>();
    // 6. softmax
    softmax_kernel<<<NBH, 64>>>(temp);
    // 7. A@V (smem-staged coalesced bf16 hi/lo stores)
    av_kernel<<<dim3(HWN/256, NBH), 256, AV_SMEM>>>();
    // 8. output projection on tensor cores
    proj_gemm_tc<<<dim3(HWN/BN, CH/BM, BATCH), 256, GEMM_SMEM>>>(out);
}

// round 17
// speedup vs baseline: 1.2402x; 1.1064x over previous
#include <cuda_runtime.h>
#include <cuda_bf16.h>
#include <math.h>
#include <stdint.h>

#define BATCH 4
#define CH    384
#define IMG   128
#define HWN   (IMG*IMG)      // 16384
#define NH    8
#define HD    48
#define NBH   (BATCH*NH)     // 32
#define GRAM_CHUNKS 32
#define NCHUNK (HWN/GRAM_CHUNKS)
#define KTOT  384

// ---------------- scratch (device globals; no allocation) ----------------
__device__ __align__(16) float g_pre  [3ull*BATCH*CH*HWN];
__device__ __align__(16) float g_post [3ull*BATCH*CH*HWN];
__device__ __align__(16) float g_snp  [2*BATCH*CH*16];
__device__ __align__(16) float g_sqn  [2*BATCH*CH];
__device__ __align__(16) float g_gpart[(size_t)GRAM_CHUNKS*NBH*HD*HD];
__device__ __align__(16) float g_gram [NBH*HD*HD];
// bf16 split operands
__device__ __align__(16) unsigned short g_wh  [(size_t)1152*KTOT];   // qkv weights hi
__device__ __align__(16) unsigned short g_wl  [(size_t)1152*KTOT];
__device__ __align__(16) unsigned short g_mh  [(size_t)BATCH*CH*CH]; // fused proj*attn hi
__device__ __align__(16) unsigned short g_ml  [(size_t)BATCH*CH*CH];
__device__ __align__(16) unsigned short g_inth[(size_t)2*BATCH*HWN*CH];  // [inp][b][p][c]
__device__ __align__(16) unsigned short g_intl[(size_t)2*BATCH*HWN*CH];
__device__ __align__(16) unsigned short g_vh  [(size_t)BATCH*HWN*CH];    // V^T [b][p][c]
__device__ __align__(16) unsigned short g_vl  [(size_t)BATCH*HWN*CH];

// ---------------- PTX helpers (sm_80-level only) ----------------
__device__ __forceinline__ uint32_t smem_u32(const void* p) {
    uint32_t a;
    asm("{ .reg .u64 t; cvta.to.shared.u64 t, %1; cvt.u32.u64 %0, t; }" : "=r"(a) : "l"(p));
    return a;
}
__device__ __forceinline__ void cpa16(uint32_t saddr, const void* gptr) {
    asm volatile("cp.async.cg.shared.global [%0], [%1], 16;" :: "r"(saddr), "l"(gptr));
}
__device__ __forceinline__ void ldm_x4(uint32_t* r, uint32_t addr) {
    asm volatile("ldmatrix.sync.aligned.m8n8.x4.shared.b16 {%0,%1,%2,%3}, [%4];"
        : "=r"(r[0]), "=r"(r[1]), "=r"(r[2]), "=r"(r[3]) : "r"(addr));
}
__device__ __forceinline__ void ldm_x2(uint32_t* r, uint32_t addr) {
    asm volatile("ldmatrix.sync.aligned.m8n8.x2.shared.b16 {%0,%1}, [%2];"
        : "=r"(r[0]), "=r"(r[1]) : "r"(addr));
}
__device__ __forceinline__ void mma_bf16(float* c, const uint32_t* a, const uint32_t* b) {
    asm volatile("mma.sync.aligned.m16n8k16.row.col.f32.bf16.bf16.f32 "
        "{%0,%1,%2,%3}, {%4,%5,%6,%7}, {%8,%9}, {%0,%1,%2,%3};"
        : "+f"(c[0]), "+f"(c[1]), "+f"(c[2]), "+f"(c[3])
        : "r"(a[0]), "r"(a[1]), "r"(a[2]), "r"(a[3]), "r"(b[0]), "r"(b[1]));
}

// ---------------- mma.sync bf16x3 GEMM: C[128 x 128] tile, K=384 (R11 config) ----------------
#define BM 128
#define BN 128
#define BK 32
#define KITERS (KTOT/BK)       // 12
#define REGB   10240
#define STAGEB 40960
#define GEMM_SMEM (2*STAGEB)   // 81920

__device__ __forceinline__ void gemm_bf16x3(
    const unsigned short* __restrict__ Ah, const unsigned short* __restrict__ Al,
    const unsigned short* __restrict__ Bh, const unsigned short* __restrict__ Bl,
    float* __restrict__ Y)
{
    extern __shared__ char gsm[];
    const uint32_t smem_base = smem_u32(gsm);
    const int tid = threadIdx.x, wid = tid >> 5, lane = tid & 31;
    const int mBase = (wid >> 2) * 64;
    const int nBase = (wid & 3) * 32;

    const int aRow = lane & 15, aCol = lane >> 4;
    const int i16  = lane & 15;
    const int bRow = i16 & 7,  bCol = i16 >> 3;

    float acc[4][4][4];
#pragma unroll
    for (int mt = 0; mt < 4; mt++)
#pragma unroll
        for (int nt = 0; nt < 4; nt++)
#pragma unroll
            for (int q = 0; q < 4; q++) acc[mt][nt][q] = 0.f;

    auto load_stage = [&](int st, int k0) {
        const uint32_t sb = smem_base + (st & 1) * STAGEB;
#pragma unroll
        for (int j = 0; j < 8; j++) {
            const int idx = tid + 256 * j;
            const int region = idx >> 9;
            const int rem = idx & 511;
            const int r = rem >> 2, c = rem & 3;
            const uint32_t saddr = sb + region * REGB + r * 80 + c * 16;
            const unsigned short* gsrc;
            if      (region == 0) gsrc = Ah + (size_t)r * KTOT + k0 + c * 8;
            else if (region == 1) gsrc = Al + (size_t)r * KTOT + k0 + c * 8;
            else if (region == 2) gsrc = Bh + (size_t)r * KTOT + k0 + c * 8;
            else                  gsrc = Bl + (size_t)r * KTOT + k0 + c * 8;
            cpa16(saddr, gsrc);
        }
        asm volatile("cp.async.commit_group;" ::: "memory");
    };

    load_stage(0, 0);

    for (int it = 0; it < KITERS; it++) {
        if (it + 1 < KITERS) {
            load_stage(it + 1, (it + 1) * BK);
            asm volatile("cp.async.wait_group 1;" ::: "memory");
        } else {
            asm volatile("cp.async.wait_group 0;" ::: "memory");
        }
        __syncthreads();

        const uint32_t sb  = smem_base + (it & 1) * STAGEB;
        const uint32_t sAh = sb, sAl = sb + REGB, sBh = sb + 2*REGB, sBl = sb + 3*REGB;

#pragma unroll
        for (int ks = 0; ks < 2; ks++) {
            const uint32_t akb = ks * 32 + aCol * 16;
            const uint32_t bkb = ks * 32 + bCol * 16;
            uint32_t fBh[4][2], fBl[4][2];
#pragma unroll
            for (int nt = 0; nt < 4; nt++)
                ldm_x2(fBh[nt], sBh + (uint32_t)(nBase + nt*8 + bRow) * 80 + bkb);
#pragma unroll
            for (int nt = 0; nt < 4; nt++)
                ldm_x2(fBl[nt], sBl + (uint32_t)(nBase + nt*8 + bRow) * 80 + bkb);
#pragma unroll
            for (int mt = 0; mt < 4; mt++) {
                uint32_t aH[4], aL[4];
                ldm_x4(aH, sAh + (uint32_t)(mBase + mt*16 + aRow) * 80 + akb);
#pragma unroll
                for (int nt = 0; nt < 4; nt++) mma_bf16(acc[mt][nt], aH, fBh[nt]);
#pragma unroll
                for (int nt = 0; nt < 4; nt++) mma_bf16(acc[mt][nt], aH, fBl[nt]);
                ldm_x4(aL, sAl + (uint32_t)(mBase + mt*16 + aRow) * 80 + akb);
#pragma unroll
                for (int nt = 0; nt < 4; nt++) mma_bf16(acc[mt][nt], aL, fBh[nt]);
            }
        }
        __syncthreads();
    }

    const int gr = lane >> 2, gc = (lane & 3) * 2;
#pragma unroll
    for (int mt = 0; mt < 4; mt++) {
#pragma unroll
        for (int nt = 0; nt < 4; nt++) {
            float* d0 = Y + (size_t)(mBase + mt*16 + gr) * HWN + nBase + nt*8 + gc;
            d0[0] = acc[mt][nt][0]; d0[1] = acc[mt][nt][1];
            float* d1 = d0 + 8 * HWN;
            d1[0] = acc[mt][nt][2]; d1[1] = acc[mt][nt][3];
        }
    }
}

__global__ __launch_bounds__(256, 2)
void qkv_gemm_tc()
{
    const int z = blockIdx.z, s = z >> 2, b = z & 3;
    const int row0 = blockIdx.y * BM, n0 = blockIdx.x * BN;
    const size_t aoff = (size_t)(s * CH + row0) * KTOT;
    const int inp = (s == 0) ? 1 : 0;   // q comes from message
    const size_t boff = ((size_t)(inp * BATCH + b) * HWN + n0) * KTOT;
    float* Y = g_pre + ((size_t)z * CH + row0) * HWN + n0;
    gemm_bf16x3(g_wh + aoff, g_wl + aoff, g_inth + boff, g_intl + boff, Y);
}

__global__ __launch_bounds__(256, 2)
void proj_gemm_tc(float* __restrict__ out)
{
    const int b = blockIdx.z;
    const int row0 = blockIdx.y * BM, n0 = blockIdx.x * BN;
    const size_t aoff = ((size_t)b * CH + row0) * CH;      // fused M[b] operand
    const size_t boff = ((size_t)b * HWN + n0) * KTOT;
    float* Y = out + ((size_t)b * CH + row0) * HWN + n0;
    gemm_bf16x3(g_mh + aoff, g_ml + aoff, g_vh + boff, g_vl + boff, Y);
}

// ---------------- convert qkv weights to bf16 hi/lo ----------------
__global__ __launch_bounds__(256) void wconv_kernel(const float* __restrict__ wqkv)
{
    const size_t i = (size_t)blockIdx.x * 256 + threadIdx.x;   // < 1152*384
    const float f = wqkv[i];
    const uint32_t bits = __float_as_uint(f);
    const float hi = __uint_as_float(bits & 0xFFFF0000u);
    const __nv_bfloat16 lo = __float2bfloat16(f - hi);
    g_wh[i] = (unsigned short)(bits >> 16);
    g_wl[i] = *(const unsigned short*)&lo;
}

// ---------------- transpose + convert one fp32 [c][p] slab -> [p][c] hi/lo ----------------
// mode 0: src=xsrc (x),   dst=g_inth/g_intl slot 0
// mode 1: src=xsrc (msg), dst=g_inth/g_intl slot 1
// mode 2: src=g_post slot 2 (V), dst=g_vh/g_vl      (ALL g_* resolved in device code)
__global__ __launch_bounds__(256) void trx_kernel(const float* __restrict__ xsrc, int mode)
{
    __shared__ float t[32][33];
    const int b = blockIdx.z;
    const int p0 = blockIdx.x * 32, c0 = blockIdx.y * 32;
    const int tx = threadIdx.x, ty = threadIdx.y;

    const float* src;
    unsigned short *dh, *dl;
    if (mode == 2) {
        src = g_post + ((size_t)((2*BATCH + b) * CH) + c0) * HWN + p0;
        dh  = g_vh + ((size_t)b * HWN + p0) * CH + c0;
        dl  = g_vl + ((size_t)b * HWN + p0) * CH + c0;
    } else {
        src = xsrc + ((size_t)b * CH + c0) * HWN + p0;
        const int z = mode * BATCH + b;
        dh  = g_inth + ((size_t)z * HWN + p0) * CH + c0;
        dl  = g_intl + ((size_t)z * HWN + p0) * CH + c0;
    }

    for (int yy = ty; yy < 32; yy += 8) t[yy][tx] = src[(size_t)yy * HWN + tx];
    __syncthreads();
    for (int yy = ty; yy < 32; yy += 8) {
        const float f = t[tx][yy];
        const uint32_t bits = __float_as_uint(f);
        const float hi = __uint_as_float(bits & 0xFFFF0000u);
        const __nv_bfloat16 lo = __float2bfloat16(f - hi);
        dh[(size_t)yy * CH + tx] = (unsigned short)(bits >> 16);
        dl[(size_t)yy * CH + tx] = *(const unsigned short*)&lo;
    }
}

// ---------------- depthwise 3x3: 2 output rows/thread, shfl neighbors ----------------
__global__ __launch_bounds__(256)
void dwconv_kernel(const float* __restrict__ wdw)
{
    __shared__ float red[8];

    const int zc = blockIdx.z;
    const int z  = zc / CH;
    const int c  = zc % CH;
    const int s  = z / BATCH;
    const float* wk = wdw + (size_t)(s*CH + c) * 9;
    const float* in   = g_pre  + (size_t)zc * HWN;
    float*       outp = g_post + (size_t)zc * HWN;

    float w[9];
#pragma unroll
    for (int i = 0; i < 9; i++) w[i] = __ldg(&wk[i]);

    const int lane = threadIdx.x;
    const int wy   = threadIdx.y;
    const int px0 = lane * 4;
    const int py0 = blockIdx.y * 16 + wy * 2;

    float r[4][6];
#pragma unroll
    for (int ky = 0; ky < 4; ky++) {
        const int iy = py0 + ky - 1;
        if (iy < 0 || iy >= IMG) {
#pragma unroll
            for (int e = 0; e < 6; e++) r[ky][e] = 0.f;
        } else {
            const float4 v = *(const float4*)(in + (size_t)iy * IMG + px0);
            float left  = __shfl_up_sync(0xffffffffu, v.w, 1);
            float right = __shfl_down_sync(0xffffffffu, v.x, 1);
            if (lane == 0)  left  = 0.f;
            if (lane == 31) right = 0.f;
            r[ky][0] = left;  r[ky][1] = v.x; r[ky][2] = v.y;
            r[ky][3] = v.z;   r[ky][4] = v.w; r[ky][5] = right;
        }
    }

    float loc = 0.f;
#pragma unroll
    for (int row = 0; row < 2; row++) {
        float a0 = 0.f, a1 = 0.f, a2 = 0.f, a3 = 0.f;
#pragma unroll
        for (int ky = 0; ky < 3; ky++) {
#pragma unroll
            for (int kx = 0; kx < 3; kx++) {
                const float wv = w[ky*3 + kx];
                a0 += r[row + ky][0 + kx] * wv;
                a1 += r[row + ky][1 + kx] * wv;
                a2 += r[row + ky][2 + kx] * wv;
                a3 += r[row + ky][3 + kx] * wv;
            }
        }
        *(float4*)(outp + (size_t)(py0 + row) * IMG + px0) = make_float4(a0, a1, a2, a3);
        loc += a0*a0 + a1*a1 + a2*a2 + a3*a3;
    }

    const int tid = wy * 32 + lane;
#pragma unroll
    for (int o = 16; o > 0; o >>= 1) loc += __shfl_xor_sync(0xffffffffu, loc, o);
    if ((tid & 31) == 0) red[tid >> 5] = loc;
    __syncthreads();
    if (tid == 0 && s < 2) {
        float t = 0.f;
#pragma unroll
        for (int i = 0; i < 8; i++) t += red[i];
        g_snp[(size_t)zc * 8 + blockIdx.y] = t;
    }
}

// ---------------- reduce sqnorm partials ----------------
__global__ __launch_bounds__(256)
void sqnorm_kernel()
{
    const int r = blockIdx.x * 256 + threadIdx.x;
    if (r >= 2*BATCH*CH) return;
    float s = 0.f;
#pragma unroll
    for (int i = 0; i < 8; i++) s += g_snp[(size_t)r * 8 + i];
    g_sqn[r] = s;
}

// ---------------- Gram partials: 8x8 threads, 6x6 per thread ----------------
__global__ __launch_bounds__(64)
void gram_kernel()
{
    __shared__ __align__(16) float qs[48][65];
    __shared__ __align__(16) float ks[48][65];

    const int bh = blockIdx.y;
    const int b  = bh >> 3;
    const int h  = bh & 7;
    const int n0 = blockIdx.x * NCHUNK;
    const float* qbase = g_post + ((size_t)(0*BATCH + b)*CH + h*HD) * HWN;
    const float* kbase = g_post + ((size_t)(1*BATCH + b)*CH + h*HD) * HWN;
    const int tid = threadIdx.y * 8 + threadIdx.x;
    const int i0 = threadIdx.y * 6;
    const int j0 = threadIdx.x * 6;

    float acc[6][6];
#pragma unroll
    for (int r = 0; r < 6; r++)
#pragma unroll
        for (int c = 0; c < 6; c++) acc[r][c] = 0.f;

    for (int t = 0; t < NCHUNK; t += 64) {
        for (int e = tid; e < 48*16; e += 64) {
            const int i = e >> 4, j4 = (e & 15) * 4;
            const float4 qv = *(const float4*)&qbase[(size_t)i*HWN + n0 + t + j4];
            const float4 kv = *(const float4*)&kbase[(size_t)i*HWN + n0 + t + j4];
            qs[i][j4+0] = qv.x; qs[i][j4+1] = qv.y; qs[i][j4+2] = qv.z; qs[i][j4+3] = qv.w;
            ks[i][j4+0] = kv.x; ks[i][j4+1] = kv.y; ks[i][j4+2] = kv.z; ks[i][j4+3] = kv.w;
        }
        __syncthreads();
#pragma unroll 4
        for (int nn = 0; nn < 64; nn++) {
            float q[6], k[6];
#pragma unroll
            for (int r = 0; r < 6; r++) q[r] = qs[i0+r][nn];
#pragma unroll
            for (int c = 0; c < 6; c++) k[c] = ks[j0+c][nn];
#pragma unroll
            for (int r = 0; r < 6; r++)
#pragma unroll
                for (int c = 0; c < 6; c++) acc[r][c] += q[r] * k[c];
        }
        __syncthreads();
    }

    float* gp = g_gpart + ((size_t)blockIdx.x * NBH + bh) * (HD*HD);
#pragma unroll
    for (int r = 0; r < 6; r++)
#pragma unroll
        for (int c = 0; c < 6; c++)
            gp[(i0+r)*HD + (j0+c)] = acc[r][c];
}

__global__ __launch_bounds__(1024)
void gram_reduce_kernel()
{
    const int idx = blockIdx.x * 1024 + threadIdx.x;
    float s = 0.f;
#pragma unroll
    for (int ch = 0; ch < GRAM_CHUNKS; ch++)
        s += g_gpart[(size_t)ch * NBH * (HD*HD) + idx];
    g_gram[idx] = s;
}

// ---------------- normalize + temperature + softmax ----------------
__global__ __launch_bounds__(64)
void softmax_kernel(const float* __restrict__ temp)
{
    const int bh = blockIdx.x;
    const int b  = bh >> 3;
    const int h  = bh & 7;
    const int i  = threadIdx.x;
    if (i >= HD) return;

    float* gg = g_gram + (size_t)bh * (HD*HD) + i*HD;
    const float invq = rsqrtf(fmaxf(g_sqn[b*CH + h*HD + i], 1e-24f));
    const float T = temp[h];

    float row[HD];
    float m = -3.4e38f;
#pragma unroll
    for (int j = 0; j < HD; j++) {
        const float invk = rsqrtf(fmaxf(g_sqn[(BATCH + b)*CH + h*HD + j], 1e-24f));
        const float v = gg[j] * invq * invk * T;
        row[j] = v;
        m = fmaxf(m, v);
    }
    float sum = 0.f;
#pragma unroll
    for (int j = 0; j < HD; j++) { row[j] = expf(row[j] - m); sum += row[j]; }
    const float inv = 1.f / sum;
#pragma unroll
    for (int j = 0; j < HD; j++) gg[j] = row[j] * inv;
}

// ---------------- fused projection: M[b][o][h*48+j] = sum_i Wp[o][h*48+i]*A[bh][i][j] ----------------
__global__ __launch_bounds__(384)
void pm_kernel(const float* __restrict__ wproj)
{
    const int o = blockIdx.x;          // 0..383
    const int b = blockIdx.y;          // 0..3
    const int tid = threadIdx.x;       // 0..383
    const int h = tid / HD;            // 0..7
    const int j = tid % HD;            // 0..47

    const float* wrow = wproj + (size_t)o * CH + h * HD;
    const float* arow = g_gram + (size_t)(b * NH + h) * (HD*HD) + j;

    float s = 0.f;
#pragma unroll 8
    for (int i = 0; i < HD; i++)
        s += wrow[i] * arow[(size_t)i * HD];

    const uint32_t bits = __float_as_uint(s);
    const float hi = __uint_as_float(bits & 0xFFFF0000u);
    const __nv_bfloat16 lo = __float2bfloat16(s - hi);
    const size_t idx = ((size_t)b * CH + o) * CH + tid;
    g_mh[idx] = (unsigned short)(bits >> 16);
    g_ml[idx] = *(const unsigned short*)&lo;
}

// ---------------- launch ----------------
extern "C" void kernel_launch(void* const* d_in, const int* in_sizes, int n_in,
                              void* d_out, int out_size)
{
    const float* x      = (const float*)d_in[0];
    const float* msg    = (const float*)d_in[1];
    const float* w_qkv  = (const float*)d_in[2];
    const float* w_dw   = (const float*)d_in[3];
    const float* w_proj = (const float*)d_in[4];
    const float* temp   = (const float*)d_in[5];
    float* out = (float*)d_out;

    cudaFuncSetAttribute(qkv_gemm_tc, cudaFuncAttributeMaxDynamicSharedMemorySize, GEMM_SMEM);
    cudaFuncSetAttribute(proj_gemm_tc, cudaFuncAttributeMaxDynamicSharedMemorySize, GEMM_SMEM);

    // 0. bf16 hi/lo conversions (trx split so qkv_gemm is launch #4 for ncu)
    wconv_kernel<<<(1152*KTOT)/256, 256>>>(w_qkv);
    trx_kernel<<<dim3(HWN/32, CH/32, BATCH), dim3(32,8)>>>(x,   0);
    trx_kernel<<<dim3(HWN/32, CH/32, BATCH), dim3(32,8)>>>(msg, 1);
    // 1. qkv GEMMs on tensor cores (R11 config)
    qkv_gemm_tc<<<dim3(HWN/BN, CH/BM, 3*BATCH), 256, GEMM_SMEM>>>();
    // 2. depthwise 3x3 (2 output rows/thread, fused sqnorm partials)
    dwconv_kernel<<<dim3(1, IMG/16, 3*BATCH*CH), dim3(32,8)>>>(w_dw);
    // 2b. transpose+split V for the proj GEMM (replaces av_kernel)
    trx_kernel<<<dim3(HWN/32, CH/32, BATCH), dim3(32,8)>>>(nullptr, 2);
    // 3. reduce sqnorm partials
    sqnorm_kernel<<<(2*BATCH*CH + 255)/256, 256>>>();
    // 4-5. Gram (two-phase deterministic, 6x6 register tiles)
    gram_kernel<<<dim3(GRAM_CHUNKS, NBH), dim3(8,8)>>>();
    gram_reduce_kernel<<<(NBH*HD*HD)/1024, 1024>>>();
    // 6. softmax
    softmax_kernel<<<NBH, 64>>>(temp);
    // 7. fold attention into projection: M = Wp . A (per batch, per head block)
    pm_kernel<<<dim3(CH, BATCH), 384>>>(w_proj);
    // 8. output projection on tensor cores: out = M @ V^T
    proj_gemm_tc<<<dim3(HWN/BN, CH/BM, BATCH), 256, GEMM_SMEM>>>(out);
}